// round 3
// baseline (speedup 1.0000x reference)
#include <cuda_runtime.h>
#include <cuda_bf16.h>
#include <cstdint>

#define HASH_SIZE 256
#define OFFSET_SIZE 64

// L2 policy: keep lines resident (evict_last) — applied to reused tables.
__device__ __forceinline__ uint64_t make_evict_last_policy() {
    uint64_t pol;
    asm("createpolicy.fractional.L2::evict_last.b64 %0, 1.0;" : "=l"(pol));
    return pol;
}

__device__ __forceinline__ float4 ldg_f4_last(const float4* p, uint64_t pol) {
    float4 v;
    asm("ld.global.nc.L2::cache_hint.v4.f32 {%0,%1,%2,%3}, [%4], %5;"
        : "=f"(v.x), "=f"(v.y), "=f"(v.z), "=f"(v.w)
        : "l"(p), "l"(pol));
    return v;
}

__device__ __forceinline__ int ldg_i_last(const int* p, uint64_t pol) {
    int v;
    asm("ld.global.nc.L2::cache_hint.b32 %0, [%1], %2;"
        : "=r"(v) : "l"(p), "l"(pol));
    return v;
}

__global__ __launch_bounds__(256)
void psh_kernel(const int* __restrict__ coords,
                const float4* __restrict__ hash_table,
                const int* __restrict__ offset_table,
                const float* __restrict__ m0,
                const float* __restrict__ m1,
                float4* __restrict__ out,
                int n)
{
    int q = blockIdx.x * blockDim.x + threadIdx.x;
    if (q >= n) return;

    uint64_t pol = make_evict_last_policy();

    // coords: one-touch stream -> .cs (evict-first behavior)
    int c0 = __ldcs(&coords[3 * q + 0]);
    int c1 = __ldcs(&coords[3 * q + 1]);
    int c2 = __ldcs(&coords[3 * q + 2]);

    float m1x = __ldg(&m1[0]), m1y = __ldg(&m1[1]), m1z = __ldg(&m1[2]);
    float m0x = __ldg(&m0[0]), m0y = __ldg(&m0[1]), m0z = __ldg(&m0[2]);

    // oidx = trunc(c * m1) mod 64  (power-of-2 mask == Python mod, any sign)
    int o0 = ((int)((float)c0 * m1x)) & (OFFSET_SIZE - 1);
    int o1 = ((int)((float)c1 * m1y)) & (OFFSET_SIZE - 1);
    int o2 = ((int)((float)c2 * m1z)) & (OFFSET_SIZE - 1);

    int oi = ((o0 * OFFSET_SIZE + o1) * OFFSET_SIZE + o2) * 3;
    int f0 = ldg_i_last(&offset_table[oi + 0], pol);
    int f1 = ldg_i_last(&offset_table[oi + 1], pol);
    int f2 = ldg_i_last(&offset_table[oi + 2], pol);

    // hidx = (trunc(c * m0) + offset) mod 256
    int h0 = (((int)((float)c0 * m0x)) + f0) & (HASH_SIZE - 1);
    int h1 = (((int)((float)c1 * m0y)) + f1) & (HASH_SIZE - 1);
    int h2 = (((int)((float)c2 * m0z)) + f2) & (HASH_SIZE - 1);

    int hi = (h0 * HASH_SIZE + h1) * HASH_SIZE + h2;   // < 2^24

    float4 a = ldg_f4_last(&hash_table[2 * hi + 0], pol);
    float4 b = ldg_f4_last(&hash_table[2 * hi + 1], pol);

    // output: write-once stream -> .cs
    __stcs(&out[2 * q + 0], a);
    __stcs(&out[2 * q + 1], b);
}

extern "C" void kernel_launch(void* const* d_in, const int* in_sizes, int n_in,
                              void* d_out, int out_size)
{
    const int*    coords       = (const int*)d_in[0];
    const float4* hash_table   = (const float4*)d_in[1];
    const int*    offset_table = (const int*)d_in[2];
    const float*  m0           = (const float*)d_in[3];
    const float*  m1           = (const float*)d_in[4];
    float4*       out          = (float4*)d_out;

    int n = in_sizes[0] / 3;
    int threads = 256;
    int blocks = (n + threads - 1) / threads;
    psh_kernel<<<blocks, threads>>>(coords, hash_table, offset_table, m0, m1, out, n);
}

// round 5
// speedup vs baseline: 1.0016x; 1.0016x over previous
#include <cuda_runtime.h>
#include <cuda_bf16.h>
#include <cstdint>

#define HASH_SIZE 256
#define OFFSET_SIZE 64

// One 256-bit load: the full 32B feature vector in a single exactly-one-sector
// request, .cg (L2-only, LSU path — NOT the .nc tex path suspected of 128B
// line promotion on miss).
__device__ __forceinline__ void ldg256_cg(const void* p,
                                          uint32_t& r0, uint32_t& r1, uint32_t& r2, uint32_t& r3,
                                          uint32_t& r4, uint32_t& r5, uint32_t& r6, uint32_t& r7) {
    asm("ld.global.cg.v8.b32 {%0,%1,%2,%3,%4,%5,%6,%7}, [%8];"
        : "=r"(r0), "=r"(r1), "=r"(r2), "=r"(r3),
          "=r"(r4), "=r"(r5), "=r"(r6), "=r"(r7)
        : "l"(p));
}

__device__ __forceinline__ void stg256(void* p,
                                       uint32_t r0, uint32_t r1, uint32_t r2, uint32_t r3,
                                       uint32_t r4, uint32_t r5, uint32_t r6, uint32_t r7) {
    asm volatile("st.global.v8.b32 [%0], {%1,%2,%3,%4,%5,%6,%7,%8};"
                 :: "l"(p),
                    "r"(r0), "r"(r1), "r"(r2), "r"(r3),
                    "r"(r4), "r"(r5), "r"(r6), "r"(r7)
                 : "memory");
}

__global__ __launch_bounds__(256)
void psh_kernel(const int* __restrict__ coords,
                const float* __restrict__ hash_table,
                const int* __restrict__ offset_table,
                const float* __restrict__ m0,
                const float* __restrict__ m1,
                float* __restrict__ out,
                int n)
{
    int q = blockIdx.x * blockDim.x + threadIdx.x;
    if (q >= n) return;

    // coords: one-touch stream
    int c0 = __ldcs(&coords[3 * q + 0]);
    int c1 = __ldcs(&coords[3 * q + 1]);
    int c2 = __ldcs(&coords[3 * q + 2]);

    float m1x = __ldg(&m1[0]), m1y = __ldg(&m1[1]), m1z = __ldg(&m1[2]);
    float m0x = __ldg(&m0[0]), m0y = __ldg(&m0[1]), m0z = __ldg(&m0[2]);

    // oidx = trunc(c * m1) mod 64  (power-of-2 mask == Python mod, any sign)
    int o0 = ((int)((float)c0 * m1x)) & (OFFSET_SIZE - 1);
    int o1 = ((int)((float)c1 * m1y)) & (OFFSET_SIZE - 1);
    int o2 = ((int)((float)c2 * m1z)) & (OFFSET_SIZE - 1);

    int oi = ((o0 * OFFSET_SIZE + o1) * OFFSET_SIZE + o2) * 3;
    // offset table is small (3MB) and hot — normal cached loads
    int f0 = __ldg(&offset_table[oi + 0]);
    int f1 = __ldg(&offset_table[oi + 1]);
    int f2 = __ldg(&offset_table[oi + 2]);

    // hidx = (trunc(c * m0) + offset) mod 256
    int h0 = (((int)((float)c0 * m0x)) + f0) & (HASH_SIZE - 1);
    int h1 = (((int)((float)c1 * m0y)) + f1) & (HASH_SIZE - 1);
    int h2 = (((int)((float)c2 * m0z)) + f2) & (HASH_SIZE - 1);

    long long hi = (long long)((h0 * HASH_SIZE + h1) * HASH_SIZE + h2);

    uint32_t r0, r1, r2, r3, r4, r5, r6, r7;
    ldg256_cg(hash_table + hi * 8, r0, r1, r2, r3, r4, r5, r6, r7);
    stg256(out + (long long)q * 8, r0, r1, r2, r3, r4, r5, r6, r7);
}

extern "C" void kernel_launch(void* const* d_in, const int* in_sizes, int n_in,
                              void* d_out, int out_size)
{
    const int*   coords       = (const int*)d_in[0];
    const float* hash_table   = (const float*)d_in[1];
    const int*   offset_table = (const int*)d_in[2];
    const float* m0           = (const float*)d_in[3];
    const float* m1           = (const float*)d_in[4];
    float*       out          = (float*)d_out;

    int n = in_sizes[0] / 3;
    int threads = 256;
    int blocks = (n + threads - 1) / threads;
    psh_kernel<<<blocks, threads>>>(coords, hash_table, offset_table, m0, m1, out, n);
}